// round 14
// baseline (speedup 1.0000x reference)
#include <cuda_runtime.h>
#include <math.h>

#define BMAX 4
#define NMAX 2048
#define MAXIT 11
#define TOLD 1e-4
#define NB 128          // persistent blocks (<= SM count, 1 block/SM resident)
#define NT 512          // threads per block
#define QTL 256         // queries per tile
#define RTL 512         // refs per tile
#define RCH 64          // refs per chunk (RTL / 8 chunks)

// ---------------- persistent device state (no allocations allowed) ----------
__device__ float g_pc[BMAX * NMAX * 3];                // temp_pc (L2-coherent)
__device__ unsigned long long g_pack[2][BMAX * NMAX];  // ping-pong argmin bufs
__device__ float g_errpart[BMAX];                      // per-batch err sums
__device__ unsigned g_cnt[3];                          // barrier slots
__device__ unsigned g_dep;

// ---------------- fence-free barrier primitives ------------------------------
__device__ __forceinline__ void arrive_release(unsigned* p) {
    asm volatile("red.release.gpu.add.u32 [%0], 1;" :: "l"(p) : "memory");
}
__device__ __forceinline__ unsigned poll_acquire(unsigned* p) {
    unsigned v;
    asm volatile("ld.acquire.gpu.u32 %0, [%1];" : "=r"(v) : "l"(p) : "memory");
    return v;
}

__device__ __forceinline__ void gbar_slot(int s, int blk) {
    __syncthreads();
    if (threadIdx.x == 0) {
        arrive_release(&g_cnt[s]);
        while (poll_acquire(&g_cnt[s]) < (unsigned)NB) { }
        if (blk == 0) g_cnt[(s + 2) % 3] = 0;
    }
    __syncthreads();
}

__device__ __forceinline__ void gbar_exit(int s, int blk) {
    __syncthreads();
    if (threadIdx.x == 0) {
        arrive_release(&g_cnt[s]);
        while (poll_acquire(&g_cnt[s]) < (unsigned)NB) { }
        arrive_release(&g_dep);
        if (blk == 0) {
            while (poll_acquire(&g_dep) < (unsigned)NB) { }
            g_cnt[0] = 0; g_cnt[1] = 0; g_cnt[2] = 0;
            g_dep = 0;
        }
    }
    __syncthreads();
}

// ---------------- Kabsch (fp32, MUFU fast-math), reference semantics --------
__device__ void kabsch3x3f(const float* __restrict__ H,
                           const float* __restrict__ c1,
                           const float* __restrict__ c2,
                           float* __restrict__ Rout,
                           float* __restrict__ tout) {
    float A[3][3];
#pragma unroll
    for (int i = 0; i < 3; i++)
#pragma unroll
        for (int j = 0; j < 3; j++)
            A[i][j] = H[0 * 3 + i] * H[0 * 3 + j] +
                      H[1 * 3 + i] * H[1 * 3 + j] +
                      H[2 * 3 + i] * H[2 * 3 + j];
    float V[3][3] = {{1, 0, 0}, {0, 1, 0}, {0, 0, 1}};
#pragma unroll 1
    for (int sweep = 0; sweep < 8; sweep++) {
        float offd = A[0][1] * A[0][1] + A[0][2] * A[0][2] + A[1][2] * A[1][2];
        float diag = A[0][0] * A[0][0] + A[1][1] * A[1][1] + A[2][2] * A[2][2];
        if (offd < 1e-13f * diag + 1e-37f) break;   // converged to fp32 eps
#pragma unroll
        for (int pi = 0; pi < 3; pi++) {
            const int p = (pi == 2) ? 1 : 0;
            const int q = (pi == 0) ? 1 : 2;
            const int r = 3 - p - q;
            float apq = A[p][q];
            if (fabsf(apq) > 1e-30f) {
                float theta = __fdividef(A[q][q] - A[p][p], 2.0f * apq);
                float th2 = fmaf(theta, theta, 1.0f);
                float sq = (th2 < 3e37f) ? th2 * __frsqrt_rn(th2)
                                         : fabsf(theta);
                float tt = __fdividef(1.0f, fabsf(theta) + sq);
                if (theta < 0.0f) tt = -tt;
                float cc = __frsqrt_rn(fmaf(tt, tt, 1.0f));
                float ss = tt * cc;
                float app = A[p][p], aqq = A[q][q];
                A[p][p] = app - tt * apq;
                A[q][q] = aqq + tt * apq;
                A[p][q] = 0.0f; A[q][p] = 0.0f;
                float arp = A[r][p], arq = A[r][q];
                A[r][p] = cc * arp - ss * arq; A[p][r] = A[r][p];
                A[r][q] = ss * arp + cc * arq; A[q][r] = A[r][q];
#pragma unroll
                for (int k = 0; k < 3; k++) {
                    float vp = V[k][p], vq = V[k][q];
                    V[k][p] = cc * vp - ss * vq;
                    V[k][q] = ss * vp + cc * vq;
                }
            }
        }
    }
    float lam[3] = {A[0][0], A[1][1], A[2][2]};
#define CSWAP_(a, b)                                                       \
    if (lam[a] < lam[b]) {                                                 \
        float tl = lam[a]; lam[a] = lam[b]; lam[b] = tl;                   \
        float t0 = V[0][a]; V[0][a] = V[0][b]; V[0][b] = t0;               \
        float t1 = V[1][a]; V[1][a] = V[1][b]; V[1][b] = t1;               \
        float t2 = V[2][a]; V[2][a] = V[2][b]; V[2][b] = t2;               \
    }
    CSWAP_(0, 1); CSWAP_(0, 2); CSWAP_(1, 2);
#undef CSWAP_
    float U[3][3];
#pragma unroll
    for (int i = 0; i < 3; i++) {
        float ux = H[0] * V[0][i] + H[1] * V[1][i] + H[2] * V[2][i];
        float uy = H[3] * V[0][i] + H[4] * V[1][i] + H[5] * V[2][i];
        float uz = H[6] * V[0][i] + H[7] * V[1][i] + H[8] * V[2][i];
        float nn2 = ux * ux + uy * uy + uz * uz;
        if (nn2 > 1e-24f) {
            float inv = __frsqrt_rn(nn2);
            U[0][i] = ux * inv; U[1][i] = uy * inv; U[2][i] = uz * inv;
        } else {
            int a = (i + 1) % 3, b2 = (i + 2) % 3;
            U[0][i] = U[1][a] * U[2][b2] - U[2][a] * U[1][b2];
            U[1][i] = U[2][a] * U[0][b2] - U[0][a] * U[2][b2];
            U[2][i] = U[0][a] * U[1][b2] - U[1][a] * U[0][b2];
        }
    }
    float detU = U[0][0] * (U[1][1] * U[2][2] - U[1][2] * U[2][1]) -
                 U[0][1] * (U[1][0] * U[2][2] - U[1][2] * U[2][0]) +
                 U[0][2] * (U[1][0] * U[2][1] - U[1][1] * U[2][0]);
    float detV = V[0][0] * (V[1][1] * V[2][2] - V[1][2] * V[2][1]) -
                 V[0][1] * (V[1][0] * V[2][2] - V[1][2] * V[2][0]) +
                 V[0][2] * (V[1][0] * V[2][1] - V[1][1] * V[2][0]);
    float d = (detU * detV < 0.0f) ? -1.0f : 1.0f;
    V[2][2] *= d;
#pragma unroll
    for (int j = 0; j < 3; j++)
#pragma unroll
        for (int k = 0; k < 3; k++)
            Rout[j * 3 + k] =
                U[k][0] * V[j][0] + U[k][1] * V[j][1] + U[k][2] * V[j][2];
#pragma unroll
    for (int k = 0; k < 3; k++)
        tout[k] = c2[k] - (c1[0] * Rout[0 * 3 + k] +
                           c1[1] * Rout[1 * 3 + k] +
                           c1[2] * Rout[2 * 3 + k]);
}

// ---------------- block-level NV-way sum helper (NT threads) ----------------
template <int NV>
__device__ void block_reduce(float* acc, float* sfin, float (*sred)[16]) {
    int tid = threadIdx.x;
#pragma unroll
    for (int v = 0; v < NV; v++)
#pragma unroll
        for (int off = 16; off > 0; off >>= 1)
            acc[v] += __shfl_down_sync(0xFFFFFFFFu, acc[v], off);
    int w = tid >> 5, lane = tid & 31;
    if (lane == 0)
#pragma unroll
        for (int v = 0; v < NV; v++) sred[w][v] = acc[v];
    __syncthreads();
    if (tid < NV) {
        float sv = 0.0f;
#pragma unroll
        for (int k = 0; k < NT / 32; k++) sv += sred[k][tid];
        sfin[tid] = sv;
    }
    __syncthreads();
}

// ---------------- the whole ICP in one persistent kernel --------------------
__global__ __launch_bounds__(NT, 1) void icp_kernel(const float* __restrict__ p1,
                                                    const float* __restrict__ p2,
                                                    float* __restrict__ out,
                                                    int N, int B) {
    __shared__ float4 sref[RTL];                    // 8 KB: (-2x,-2y,-2z,|s|^2)
    __shared__ unsigned long long skey[8][QTL];     // 16 KB
    __shared__ float sred[NT / 32][16];
    __shared__ float sfin[16];
    __shared__ float sRt[12];
    __shared__ int sdone;
    int tid = threadIdx.x, blk = blockIdx.x;
    int kbar = 0;
    int total = B * N;
    double prev_err = 0.0;                          // tracked by tid 0 only

    // ---- init: g_pc = p1, both pack buffers = inf (all via L2) ----
    for (int i = blk * NT + tid; i < total; i += NB * NT) {
        __stcg(&g_pc[i * 3 + 0], p1[i * 3 + 0]);
        __stcg(&g_pc[i * 3 + 1], p1[i * 3 + 1]);
        __stcg(&g_pc[i * 3 + 2], p1[i * 3 + 2]);
        __stcg(&g_pack[0][i], ~0ull);
        __stcg(&g_pack[1][i], ~0ull);
    }
    gbar_slot(kbar % 3, blk); kbar++;

    int nIT = (N + QTL - 1) / QTL;
    int nJC = (N + RTL - 1) / RTL;
    int ntiles = B * nIT * nJC;

    for (int it = 0; it < MAXIT; it++) {
        // done check: every block computes the same mean from g_errpart
        if (it > 0) {
            if (tid == 0) {
                double s = 0.0;
                for (int bb = 0; bb < B; bb++)
                    s += (double)__ldcg(&g_errpart[bb]);
                double mean = s / (double)(B * N);
                sdone = (fabs(prev_err - mean) < TOLD) ? 1 : 0;
                prev_err = mean;
            }
            __syncthreads();
            if (sdone) break;                       // uniform across blocks
        }
        int par = it & 1;
        unsigned long long* pk_cur = g_pack[par];
        unsigned long long* pk_nxt = g_pack[par ^ 1];

        // ---- NN phase: tile = 256 queries x 512 refs; 4 queries/thread ----
        for (int tile = blk; tile < ntiles; tile += NB) {
            int b = tile / (nIT * nJC);
            int r = tile % (nIT * nJC);
            int ti = r / nJC, tj = r % nJC;
            int j0 = tj * RTL;
            __syncthreads();                       // smem reuse guard
            // load refs as (-2x, -2y, -2z, |s|^2): score = 3 nested FMA
            for (int j = tid; j < RTL; j += NT) {
                int jj = j0 + j;
                float4 v;
                if (jj < N) {
                    const float* p = &g_pc[(b * N + jj) * 3];
                    float x = __ldcg(p + 0), y = __ldcg(p + 1),
                          z = __ldcg(p + 2);
                    v.w = x * x + y * y + z * z;
                    v.x = -2.0f * x; v.y = -2.0f * y; v.z = -2.0f * z;
                } else { v.x = 0.f; v.y = 0.f; v.z = 0.f; v.w = 3.0e38f; }
                sref[j] = v;
            }
            __syncthreads();

            int qg = tid & 63;                     // query group 0..63
            int c = tid >> 6;                      // ref chunk 0..7
            int i0 = ti * QTL + qg * 4;
            float qx[4], qy[4], qz[4];
            bool qv = (i0 + 3 < N);
            if (qv) {
                // 4 consecutive queries = 48B aligned -> 3x LDG.128 (L1 hot)
                const float4* qp =
                    (const float4*)&p2[(b * N + i0) * 3];
                float4 a0 = qp[0], a1 = qp[1], a2 = qp[2];
                qx[0] = a0.x; qy[0] = a0.y; qz[0] = a0.z;
                qx[1] = a0.w; qy[1] = a1.x; qz[1] = a1.y;
                qx[2] = a1.z; qy[2] = a1.w; qz[2] = a2.x;
                qx[3] = a2.y; qy[3] = a2.z; qz[3] = a2.w;
            } else {
#pragma unroll
                for (int k = 0; k < 4; k++) {
                    int i = i0 + k;
                    if (i < N) {
                        const float* qq = &p2[(b * N + i) * 3];
                        qx[k] = qq[0]; qy[k] = qq[1]; qz[k] = qq[2];
                    } else { qx[k] = 0.f; qy[k] = 0.f; qz[k] = 0.f; }
                }
            }
            int jb = c * RCH;
            // ---- pass 1: min score via FMNMX chains (branch/pred free) ----
            float bs[4] = {3.4e38f, 3.4e38f, 3.4e38f, 3.4e38f};
#pragma unroll 4
            for (int j = 0; j < RCH; j++) {
                float4 s = sref[jb + j];
#pragma unroll
                for (int k = 0; k < 4; k++) {
                    float sc = fmaf(qx[k], s.x,
                                    fmaf(qy[k], s.y, fmaf(qz[k], s.z, s.w)));
                    bs[k] = fminf(bs[k], sc);
                }
            }
            // ---- pass 2: first index with sc == min (IMNMX chains) --------
            int bj[4] = {0x7FFFFFFF, 0x7FFFFFFF, 0x7FFFFFFF, 0x7FFFFFFF};
#pragma unroll 4
            for (int j = 0; j < RCH; j++) {
                float4 s = sref[jb + j];
#pragma unroll
                for (int k = 0; k < 4; k++) {
                    float sc = fmaf(qx[k], s.x,
                                    fmaf(qy[k], s.y, fmaf(qz[k], s.z, s.w)));
                    int cand = (sc == bs[k]) ? j : 0x7FFFFFFF;
                    bj[k] = min(bj[k], cand);
                }
            }
#pragma unroll
            for (int k = 0; k < 4; k++) {
                unsigned ub = __float_as_uint(bs[k]);
                ub ^= (ub & 0x80000000u) ? 0xFFFFFFFFu : 0x80000000u;
                skey[c][qg * 4 + k] =
                    ((unsigned long long)ub << 32) | (unsigned)(jb + bj[k]);
            }
            __syncthreads();
            // combine 8 chunks per query; recompute exact d2 for the winner
            if (tid < QTL) {
                int i = ti * QTL + tid;
                if (i < N) {
                    unsigned long long kmin = skey[0][tid];
#pragma unroll
                    for (int cc = 1; cc < 8; cc++) {
                        unsigned long long k2 = skey[cc][tid];
                        if (k2 < kmin) kmin = k2;
                    }
                    int jloc = (int)(unsigned)(kmin & 0xFFFFFFFFull);
                    float4 s = sref[jloc];
                    float x = -0.5f * s.x, y = -0.5f * s.y, z = -0.5f * s.z;
                    const float* qq = &p2[(b * N + i) * 3];
                    float dx = qq[0] - x, dy = qq[1] - y, dz = qq[2] - z;
                    float d2 = fmaf(dx, dx, fmaf(dy, dy, dz * dz));
                    unsigned long long pk =
                        ((unsigned long long)__float_as_uint(d2) << 32) |
                        (unsigned)(j0 + jloc);
                    atomicMin(&pk_cur[b * N + i], pk);
                }
            }
        }
        gbar_slot(kbar % 3, blk); kbar++;

        // ---- phase B (blocks 0..B-1): hsum+err + kabsch + apply + reset ----
        if (blk < B) {
            int b = blk;
            float acc[16];
#pragma unroll
            for (int v = 0; v < 16; v++) acc[v] = 0.0f;
            for (int n = tid; n < N; n += NT) {
                const float* pc = &g_pc[(b * N + n) * 3];
                float ax = __ldcg(pc + 0), ay = __ldcg(pc + 1),
                      az = __ldcg(pc + 2);
                unsigned long long pkL = __ldcg(&pk_cur[(B - 1) * N + n]);
                int mi = (int)(unsigned)(pkL & 0xFFFFFFFFull);
                const float* m = &p2[(b * N + mi) * 3];
                float bx = m[0], by = m[1], bz = m[2];
                unsigned long long pkb = __ldcg(&pk_cur[b * N + n]);
                float d2 = __uint_as_float((unsigned)(pkb >> 32));
                acc[0] += ax;  acc[1] += ay;  acc[2] += az;
                acc[3] += bx;  acc[4] += by;  acc[5] += bz;
                acc[6] += bx * ax;  acc[7] += bx * ay;  acc[8] += bx * az;
                acc[9] += by * ax;  acc[10] += by * ay; acc[11] += by * az;
                acc[12] += bz * ax; acc[13] += bz * ay; acc[14] += bz * az;
                acc[15] += sqrtf(d2);
            }
            block_reduce<16>(acc, sfin, sred);
            if (tid == 0) {
                __stcg(&g_errpart[b], sfin[15]);
                float invN = 1.0f / (float)N;
                float H[9], c1[3], c2[3], R[9], tv[3];
#pragma unroll
                for (int j = 0; j < 3; j++)
#pragma unroll
                    for (int k = 0; k < 3; k++)
                        H[j * 3 + k] = sfin[6 + j * 3 + k] -
                                       sfin[3 + j] * sfin[k] * invN;
#pragma unroll
                for (int k = 0; k < 3; k++) {
                    c1[k] = sfin[k] * invN;
                    c2[k] = sfin[3 + k] * invN;
                }
                kabsch3x3f(H, c1, c2, R, tv);
#pragma unroll
                for (int v = 0; v < 9; v++) sRt[v] = R[v];
#pragma unroll
                for (int v = 0; v < 3; v++) sRt[9 + v] = tv[v];
            }
            __syncthreads();
            // apply to own batch + reset other pack buffer for next iteration
            for (int n = tid; n < N; n += NT) {
                float* p = &g_pc[(b * N + n) * 3];
                float x = __ldcg(p + 0), y = __ldcg(p + 1), z = __ldcg(p + 2);
                __stcg(p + 0, x * sRt[0] + y * sRt[3] + z * sRt[6] + sRt[9]);
                __stcg(p + 1, x * sRt[1] + y * sRt[4] + z * sRt[7] + sRt[10]);
                __stcg(p + 2, x * sRt[2] + y * sRt[5] + z * sRt[8] + sRt[11]);
                __stcg(&pk_nxt[b * N + n], ~0ull);
            }
        }
        gbar_slot(kbar % 3, blk); kbar++;
    }

    gbar_exit(kbar % 3, blk);   // also resets counters for graph replay

    // ---- final transform: q1 = p1, q2 = temp_pc ----
    if (blk >= B) return;
    {
        int b = blk;
        float acc[15];
#pragma unroll
        for (int v = 0; v < 15; v++) acc[v] = 0.0f;
        for (int n = tid; n < N; n += NT) {
            const float* a = &p1[(b * N + n) * 3];
            const float* c = &g_pc[(b * N + n) * 3];
            float ax = a[0], ay = a[1], az = a[2];
            float bx = __ldcg(c + 0), by = __ldcg(c + 1), bz = __ldcg(c + 2);
            acc[0] += ax;  acc[1] += ay;  acc[2] += az;
            acc[3] += bx;  acc[4] += by;  acc[5] += bz;
            acc[6] += bx * ax;  acc[7] += bx * ay;  acc[8] += bx * az;
            acc[9] += by * ax;  acc[10] += by * ay; acc[11] += by * az;
            acc[12] += bz * ax; acc[13] += bz * ay; acc[14] += bz * az;
        }
        block_reduce<15>(acc, sfin, sred);
        if (tid == 0) {
            float invN = 1.0f / (float)N;
            float H[9], c1[3], c2[3], R[9], tv[3];
#pragma unroll
            for (int j = 0; j < 3; j++)
#pragma unroll
                for (int k = 0; k < 3; k++)
                    H[j * 3 + k] = sfin[6 + j * 3 + k] -
                                   sfin[3 + j] * sfin[k] * invN;
#pragma unroll
            for (int k = 0; k < 3; k++) {
                c1[k] = sfin[k] * invN;
                c2[k] = sfin[3 + k] * invN;
            }
            kabsch3x3f(H, c1, c2, R, tv);
#pragma unroll
            for (int j = 0; j < 3; j++) {
                out[b * 12 + j * 4 + 0] = R[j * 3 + 0];
                out[b * 12 + j * 4 + 1] = R[j * 3 + 1];
                out[b * 12 + j * 4 + 2] = R[j * 3 + 2];
                out[b * 12 + j * 4 + 3] = tv[j];
            }
        }
    }
}

extern "C" void kernel_launch(void* const* d_in, const int* in_sizes, int n_in,
                              void* d_out, int out_size) {
    const float* p1 = (const float*)d_in[0];
    const float* p2 = (const float*)d_in[1];
    float* out = (float*)d_out;

    int B = out_size / 12;            // T is (B,3,4)
    if (B < 1) B = 1;
    if (B > BMAX) B = BMAX;
    int N = in_sizes[0] / (B * 3);    // points per batch
    if (N > NMAX) N = NMAX;

    icp_kernel<<<NB, NT>>>(p1, p2, out, N, B);
}

// round 15
// speedup vs baseline: 1.0967x; 1.0967x over previous
#include <cuda_runtime.h>
#include <math.h>

#define BMAX 4
#define NMAX 2048
#define MAXIT 11
#define TOLD 1e-4
#define NB 128          // persistent blocks (<= SM count, 1 block/SM resident)
#define NT 512          // threads per block
#define QTL 256         // queries per tile
#define RTL 512         // refs per tile
#define RCH 64          // refs per chunk (RTL / 8 chunks)

// ---------------- persistent device state (no allocations allowed) ----------
// g_pc4 stores temp_pc in NN-ready form: (-2x, -2y, -2z, x^2+y^2+z^2).
// Coordinates recover exactly as -0.5f * v (power-of-two multiply).
__device__ float4 g_pc4[BMAX * NMAX];
__device__ unsigned long long g_pack[2][BMAX * NMAX];  // ping-pong argmin bufs
__device__ float g_errpart[BMAX];                      // per-batch err sums
__device__ unsigned g_cnt[3];                          // barrier slots
__device__ unsigned g_dep;

// ---------------- fence-free barrier primitives ------------------------------
__device__ __forceinline__ void arrive_release(unsigned* p) {
    asm volatile("red.release.gpu.add.u32 [%0], 1;" :: "l"(p) : "memory");
}
__device__ __forceinline__ unsigned poll_acquire(unsigned* p) {
    unsigned v;
    asm volatile("ld.acquire.gpu.u32 %0, [%1];" : "=r"(v) : "l"(p) : "memory");
    return v;
}

__device__ __forceinline__ void gbar_slot(int s, int blk) {
    __syncthreads();
    if (threadIdx.x == 0) {
        arrive_release(&g_cnt[s]);
        while (poll_acquire(&g_cnt[s]) < (unsigned)NB) { }
        if (blk == 0) g_cnt[(s + 2) % 3] = 0;
    }
    __syncthreads();
}

__device__ __forceinline__ void gbar_exit(int s, int blk) {
    __syncthreads();
    if (threadIdx.x == 0) {
        arrive_release(&g_cnt[s]);
        while (poll_acquire(&g_cnt[s]) < (unsigned)NB) { }
        arrive_release(&g_dep);
        if (blk == 0) {
            while (poll_acquire(&g_dep) < (unsigned)NB) { }
            g_cnt[0] = 0; g_cnt[1] = 0; g_cnt[2] = 0;
            g_dep = 0;
        }
    }
    __syncthreads();
}

// ---------------- Kabsch (fp32, MUFU fast-math), reference semantics --------
__device__ void kabsch3x3f(const float* __restrict__ H,
                           const float* __restrict__ c1,
                           const float* __restrict__ c2,
                           float* __restrict__ Rout,
                           float* __restrict__ tout) {
    float A[3][3];
#pragma unroll
    for (int i = 0; i < 3; i++)
#pragma unroll
        for (int j = 0; j < 3; j++)
            A[i][j] = H[0 * 3 + i] * H[0 * 3 + j] +
                      H[1 * 3 + i] * H[1 * 3 + j] +
                      H[2 * 3 + i] * H[2 * 3 + j];
    float V[3][3] = {{1, 0, 0}, {0, 1, 0}, {0, 0, 1}};
#pragma unroll 1
    for (int sweep = 0; sweep < 8; sweep++) {
        float offd = A[0][1] * A[0][1] + A[0][2] * A[0][2] + A[1][2] * A[1][2];
        float diag = A[0][0] * A[0][0] + A[1][1] * A[1][1] + A[2][2] * A[2][2];
        if (offd < 1e-13f * diag + 1e-37f) break;   // converged to fp32 eps
#pragma unroll
        for (int pi = 0; pi < 3; pi++) {
            const int p = (pi == 2) ? 1 : 0;
            const int q = (pi == 0) ? 1 : 2;
            const int r = 3 - p - q;
            float apq = A[p][q];
            if (fabsf(apq) > 1e-30f) {
                float theta = __fdividef(A[q][q] - A[p][p], 2.0f * apq);
                float th2 = fmaf(theta, theta, 1.0f);
                float sq = (th2 < 3e37f) ? th2 * __frsqrt_rn(th2)
                                         : fabsf(theta);
                float tt = __fdividef(1.0f, fabsf(theta) + sq);
                if (theta < 0.0f) tt = -tt;
                float cc = __frsqrt_rn(fmaf(tt, tt, 1.0f));
                float ss = tt * cc;
                float app = A[p][p], aqq = A[q][q];
                A[p][p] = app - tt * apq;
                A[q][q] = aqq + tt * apq;
                A[p][q] = 0.0f; A[q][p] = 0.0f;
                float arp = A[r][p], arq = A[r][q];
                A[r][p] = cc * arp - ss * arq; A[p][r] = A[r][p];
                A[r][q] = ss * arp + cc * arq; A[q][r] = A[r][q];
#pragma unroll
                for (int k = 0; k < 3; k++) {
                    float vp = V[k][p], vq = V[k][q];
                    V[k][p] = cc * vp - ss * vq;
                    V[k][q] = ss * vp + cc * vq;
                }
            }
        }
    }
    float lam[3] = {A[0][0], A[1][1], A[2][2]};
#define CSWAP_(a, b)                                                       \
    if (lam[a] < lam[b]) {                                                 \
        float tl = lam[a]; lam[a] = lam[b]; lam[b] = tl;                   \
        float t0 = V[0][a]; V[0][a] = V[0][b]; V[0][b] = t0;               \
        float t1 = V[1][a]; V[1][a] = V[1][b]; V[1][b] = t1;               \
        float t2 = V[2][a]; V[2][a] = V[2][b]; V[2][b] = t2;               \
    }
    CSWAP_(0, 1); CSWAP_(0, 2); CSWAP_(1, 2);
#undef CSWAP_
    float U[3][3];
#pragma unroll
    for (int i = 0; i < 3; i++) {
        float ux = H[0] * V[0][i] + H[1] * V[1][i] + H[2] * V[2][i];
        float uy = H[3] * V[0][i] + H[4] * V[1][i] + H[5] * V[2][i];
        float uz = H[6] * V[0][i] + H[7] * V[1][i] + H[8] * V[2][i];
        float nn2 = ux * ux + uy * uy + uz * uz;
        if (nn2 > 1e-24f) {
            float inv = __frsqrt_rn(nn2);
            U[0][i] = ux * inv; U[1][i] = uy * inv; U[2][i] = uz * inv;
        } else {
            int a = (i + 1) % 3, b2 = (i + 2) % 3;
            U[0][i] = U[1][a] * U[2][b2] - U[2][a] * U[1][b2];
            U[1][i] = U[2][a] * U[0][b2] - U[0][a] * U[2][b2];
            U[2][i] = U[0][a] * U[1][b2] - U[1][a] * U[0][b2];
        }
    }
    float detU = U[0][0] * (U[1][1] * U[2][2] - U[1][2] * U[2][1]) -
                 U[0][1] * (U[1][0] * U[2][2] - U[1][2] * U[2][0]) +
                 U[0][2] * (U[1][0] * U[2][1] - U[1][1] * U[2][0]);
    float detV = V[0][0] * (V[1][1] * V[2][2] - V[1][2] * V[2][1]) -
                 V[0][1] * (V[1][0] * V[2][2] - V[1][2] * V[2][0]) +
                 V[0][2] * (V[1][0] * V[2][1] - V[1][1] * V[2][0]);
    float d = (detU * detV < 0.0f) ? -1.0f : 1.0f;
    V[2][2] *= d;
#pragma unroll
    for (int j = 0; j < 3; j++)
#pragma unroll
        for (int k = 0; k < 3; k++)
            Rout[j * 3 + k] =
                U[k][0] * V[j][0] + U[k][1] * V[j][1] + U[k][2] * V[j][2];
#pragma unroll
    for (int k = 0; k < 3; k++)
        tout[k] = c2[k] - (c1[0] * Rout[0 * 3 + k] +
                           c1[1] * Rout[1 * 3 + k] +
                           c1[2] * Rout[2 * 3 + k]);
}

// ---------------- block-level NV-way sum helper (NT threads) ----------------
template <int NV>
__device__ void block_reduce(float* acc, float* sfin, float (*sred)[16]) {
    int tid = threadIdx.x;
#pragma unroll
    for (int v = 0; v < NV; v++)
#pragma unroll
        for (int off = 16; off > 0; off >>= 1)
            acc[v] += __shfl_down_sync(0xFFFFFFFFu, acc[v], off);
    int w = tid >> 5, lane = tid & 31;
    if (lane == 0)
#pragma unroll
        for (int v = 0; v < NV; v++) sred[w][v] = acc[v];
    __syncthreads();
    if (tid < NV) {
        float sv = 0.0f;
#pragma unroll
        for (int k = 0; k < NT / 32; k++) sv += sred[k][tid];
        sfin[tid] = sv;
    }
    __syncthreads();
}

// build NN-ready form from coordinates
__device__ __forceinline__ float4 nnform(float x, float y, float z) {
    float4 v;
    v.w = x * x + y * y + z * z;
    v.x = -2.0f * x; v.y = -2.0f * y; v.z = -2.0f * z;
    return v;
}

// ---------------- the whole ICP in one persistent kernel --------------------
__global__ __launch_bounds__(NT, 1) void icp_kernel(const float* __restrict__ p1,
                                                    const float* __restrict__ p2,
                                                    float* __restrict__ out,
                                                    int N, int B) {
    __shared__ float4 sref[RTL];                    // 8 KB: NN-ready refs
    __shared__ unsigned long long skey[8][QTL];     // 16 KB
    __shared__ float sred[NT / 32][16];
    __shared__ float sfin[16];
    __shared__ float sRt[12];
    __shared__ int sdone;
    int tid = threadIdx.x, blk = blockIdx.x;
    int kbar = 0;
    int total = B * N;
    double prev_err = 0.0;                          // tracked by tid 0 only

    // ---- init: g_pc4 = NN-form(p1), both pack buffers = inf (all via L2) ---
    for (int i = blk * NT + tid; i < total; i += NB * NT) {
        float x = p1[i * 3 + 0], y = p1[i * 3 + 1], z = p1[i * 3 + 2];
        __stcg(&g_pc4[i], nnform(x, y, z));
        __stcg(&g_pack[0][i], ~0ull);
        __stcg(&g_pack[1][i], ~0ull);
    }
    gbar_slot(kbar % 3, blk); kbar++;

    int nIT = (N + QTL - 1) / QTL;
    int nJC = (N + RTL - 1) / RTL;
    int ntiles = B * nIT * nJC;

    for (int it = 0; it < MAXIT; it++) {
        // done check: every block computes the same mean from g_errpart
        if (it > 0) {
            if (tid == 0) {
                double s = 0.0;
                for (int bb = 0; bb < B; bb++)
                    s += (double)__ldcg(&g_errpart[bb]);
                double mean = s / (double)(B * N);
                sdone = (fabs(prev_err - mean) < TOLD) ? 1 : 0;
                prev_err = mean;
            }
            __syncthreads();
            if (sdone) break;                       // uniform across blocks
        }
        int par = it & 1;
        unsigned long long* pk_cur = g_pack[par];
        unsigned long long* pk_nxt = g_pack[par ^ 1];

        // ---- NN phase: tile = 256 queries x 512 refs; 4 queries/thread ----
        for (int tile = blk; tile < ntiles; tile += NB) {
            int b = tile / (nIT * nJC);
            int r = tile % (nIT * nJC);
            int ti = r / nJC, tj = r % nJC;
            int j0 = tj * RTL;
            __syncthreads();                       // smem reuse guard
            // ref load: pure LDG.128 -> STS.128 copy (NN form precomputed)
            for (int j = tid; j < RTL; j += NT) {
                int jj = j0 + j;
                float4 v;
                if (jj < N) {
                    v = __ldcg(&g_pc4[b * N + jj]);
                } else { v.x = 0.f; v.y = 0.f; v.z = 0.f; v.w = 3.0e38f; }
                sref[j] = v;
            }
            __syncthreads();

            int qg = tid & 63;                     // query group 0..63
            int c = tid >> 6;                      // ref chunk 0..7
            int i0 = ti * QTL + qg * 4;
            float qx[4], qy[4], qz[4];
            bool qv = (i0 + 3 < N);
            if (qv) {
                // 4 consecutive queries = 48B aligned -> 3x LDG.128 (L1 hot)
                const float4* qp =
                    (const float4*)&p2[(b * N + i0) * 3];
                float4 a0 = qp[0], a1 = qp[1], a2 = qp[2];
                qx[0] = a0.x; qy[0] = a0.y; qz[0] = a0.z;
                qx[1] = a0.w; qy[1] = a1.x; qz[1] = a1.y;
                qx[2] = a1.z; qy[2] = a1.w; qz[2] = a2.x;
                qx[3] = a2.y; qy[3] = a2.z; qz[3] = a2.w;
            } else {
#pragma unroll
                for (int k = 0; k < 4; k++) {
                    int i = i0 + k;
                    if (i < N) {
                        const float* qq = &p2[(b * N + i) * 3];
                        qx[k] = qq[0]; qy[k] = qq[1]; qz[k] = qq[2];
                    } else { qx[k] = 0.f; qy[k] = 0.f; qz[k] = 0.f; }
                }
            }
            float bs[4] = {3.4e38f, 3.4e38f, 3.4e38f, 3.4e38f};
            int bj[4] = {0, 0, 0, 0};
            int jb = c * RCH;
#pragma unroll 4
            for (int j = 0; j < RCH; j++) {
                float4 s = sref[jb + j];
#pragma unroll
                for (int k = 0; k < 4; k++) {
                    float sc = fmaf(qx[k], s.x,
                                    fmaf(qy[k], s.y, fmaf(qz[k], s.z, s.w)));
                    if (sc < bs[k]) { bs[k] = sc; bj[k] = j; }  // strict: first
                }
            }
#pragma unroll
            for (int k = 0; k < 4; k++) {
                unsigned ub = __float_as_uint(bs[k]);
                ub ^= (ub & 0x80000000u) ? 0xFFFFFFFFu : 0x80000000u;
                skey[c][qg * 4 + k] =
                    ((unsigned long long)ub << 32) | (unsigned)(jb + bj[k]);
            }
            __syncthreads();
            // combine 8 chunks per query; recompute exact d2 for the winner
            if (tid < QTL) {
                int i = ti * QTL + tid;
                if (i < N) {
                    unsigned long long kmin = skey[0][tid];
#pragma unroll
                    for (int cc = 1; cc < 8; cc++) {
                        unsigned long long k2 = skey[cc][tid];
                        if (k2 < kmin) kmin = k2;
                    }
                    int jloc = (int)(unsigned)(kmin & 0xFFFFFFFFull);
                    float4 s = sref[jloc];
                    float x = -0.5f * s.x, y = -0.5f * s.y, z = -0.5f * s.z;
                    const float* qq = &p2[(b * N + i) * 3];
                    float dx = qq[0] - x, dy = qq[1] - y, dz = qq[2] - z;
                    float d2 = fmaf(dx, dx, fmaf(dy, dy, dz * dz));
                    unsigned long long pk =
                        ((unsigned long long)__float_as_uint(d2) << 32) |
                        (unsigned)(j0 + jloc);
                    atomicMin(&pk_cur[b * N + i], pk);
                }
            }
        }
        gbar_slot(kbar % 3, blk); kbar++;

        // ---- phase B (blocks 0..B-1): hsum+err + kabsch + apply + reset ----
        if (blk < B) {
            int b = blk;
            float acc[16];
#pragma unroll
            for (int v = 0; v < 16; v++) acc[v] = 0.0f;
            for (int n = tid; n < N; n += NT) {
                float4 pc4 = __ldcg(&g_pc4[b * N + n]);
                float ax = -0.5f * pc4.x, ay = -0.5f * pc4.y,
                      az = -0.5f * pc4.z;                  // exact recovery
                unsigned long long pkL = __ldcg(&pk_cur[(B - 1) * N + n]);
                int mi = (int)(unsigned)(pkL & 0xFFFFFFFFull);
                const float* m = &p2[(b * N + mi) * 3];
                float bx = m[0], by = m[1], bz = m[2];
                unsigned long long pkb = __ldcg(&pk_cur[b * N + n]);
                float d2 = __uint_as_float((unsigned)(pkb >> 32));
                acc[0] += ax;  acc[1] += ay;  acc[2] += az;
                acc[3] += bx;  acc[4] += by;  acc[5] += bz;
                acc[6] += bx * ax;  acc[7] += bx * ay;  acc[8] += bx * az;
                acc[9] += by * ax;  acc[10] += by * ay; acc[11] += by * az;
                acc[12] += bz * ax; acc[13] += bz * ay; acc[14] += bz * az;
                acc[15] += sqrtf(d2);
            }
            block_reduce<16>(acc, sfin, sred);
            if (tid == 0) {
                __stcg(&g_errpart[b], sfin[15]);
                float invN = 1.0f / (float)N;
                float H[9], c1[3], c2[3], R[9], tv[3];
#pragma unroll
                for (int j = 0; j < 3; j++)
#pragma unroll
                    for (int k = 0; k < 3; k++)
                        H[j * 3 + k] = sfin[6 + j * 3 + k] -
                                       sfin[3 + j] * sfin[k] * invN;
#pragma unroll
                for (int k = 0; k < 3; k++) {
                    c1[k] = sfin[k] * invN;
                    c2[k] = sfin[3 + k] * invN;
                }
                kabsch3x3f(H, c1, c2, R, tv);
#pragma unroll
                for (int v = 0; v < 9; v++) sRt[v] = R[v];
#pragma unroll
                for (int v = 0; v < 3; v++) sRt[9 + v] = tv[v];
            }
            __syncthreads();
            // apply to own batch (store NN form) + reset other pack buffer
            for (int n = tid; n < N; n += NT) {
                float4 pc4 = __ldcg(&g_pc4[b * N + n]);
                float x = -0.5f * pc4.x, y = -0.5f * pc4.y,
                      z = -0.5f * pc4.z;                   // exact recovery
                float nx = x * sRt[0] + y * sRt[3] + z * sRt[6] + sRt[9];
                float ny = x * sRt[1] + y * sRt[4] + z * sRt[7] + sRt[10];
                float nz = x * sRt[2] + y * sRt[5] + z * sRt[8] + sRt[11];
                __stcg(&g_pc4[b * N + n], nnform(nx, ny, nz));
                __stcg(&pk_nxt[b * N + n], ~0ull);
            }
        }
        gbar_slot(kbar % 3, blk); kbar++;
    }

    gbar_exit(kbar % 3, blk);   // also resets counters for graph replay

    // ---- final transform: q1 = p1, q2 = temp_pc ----
    if (blk >= B) return;
    {
        int b = blk;
        float acc[15];
#pragma unroll
        for (int v = 0; v < 15; v++) acc[v] = 0.0f;
        for (int n = tid; n < N; n += NT) {
            const float* a = &p1[(b * N + n) * 3];
            float4 pc4 = __ldcg(&g_pc4[b * N + n]);
            float ax = a[0], ay = a[1], az = a[2];
            float bx = -0.5f * pc4.x, by = -0.5f * pc4.y, bz = -0.5f * pc4.z;
            acc[0] += ax;  acc[1] += ay;  acc[2] += az;
            acc[3] += bx;  acc[4] += by;  acc[5] += bz;
            acc[6] += bx * ax;  acc[7] += bx * ay;  acc[8] += bx * az;
            acc[9] += by * ax;  acc[10] += by * ay; acc[11] += by * az;
            acc[12] += bz * ax; acc[13] += bz * ay; acc[14] += bz * az;
        }
        block_reduce<15>(acc, sfin, sred);
        if (tid == 0) {
            float invN = 1.0f / (float)N;
            float H[9], c1[3], c2[3], R[9], tv[3];
#pragma unroll
            for (int j = 0; j < 3; j++)
#pragma unroll
                for (int k = 0; k < 3; k++)
                    H[j * 3 + k] = sfin[6 + j * 3 + k] -
                                   sfin[3 + j] * sfin[k] * invN;
#pragma unroll
            for (int k = 0; k < 3; k++) {
                c1[k] = sfin[k] * invN;
                c2[k] = sfin[3 + k] * invN;
            }
            kabsch3x3f(H, c1, c2, R, tv);
#pragma unroll
            for (int j = 0; j < 3; j++) {
                out[b * 12 + j * 4 + 0] = R[j * 3 + 0];
                out[b * 12 + j * 4 + 1] = R[j * 3 + 1];
                out[b * 12 + j * 4 + 2] = R[j * 3 + 2];
                out[b * 12 + j * 4 + 3] = tv[j];
            }
        }
    }
}

extern "C" void kernel_launch(void* const* d_in, const int* in_sizes, int n_in,
                              void* d_out, int out_size) {
    const float* p1 = (const float*)d_in[0];
    const float* p2 = (const float*)d_in[1];
    float* out = (float*)d_out;

    int B = out_size / 12;            // T is (B,3,4)
    if (B < 1) B = 1;
    if (B > BMAX) B = BMAX;
    int N = in_sizes[0] / (B * 3);    // points per batch
    if (N > NMAX) N = NMAX;

    icp_kernel<<<NB, NT>>>(p1, p2, out, N, B);
}

// round 16
// speedup vs baseline: 1.1600x; 1.0577x over previous
#include <cuda_runtime.h>
#include <math.h>

#define BMAX 4
#define NMAX 2048
#define MAXIT 11
#define TOLD 1e-4
#define NB 128          // persistent blocks (<= SM count, 1 block/SM resident)
#define NT 512          // threads per block
#define QTL 256         // queries per tile
#define RTL 512         // refs per tile
#define RCH 64          // refs per chunk (RTL / 8 chunks); 6 index bits

// ---------------- persistent device state (no allocations allowed) ----------
// g_pc4 stores temp_pc in NN-ready form: (-2x, -2y, -2z, x^2+y^2+z^2).
__device__ float4 g_pc4[BMAX * NMAX];
__device__ unsigned long long g_pack[2][BMAX * NMAX];  // ping-pong argmin bufs
__device__ float g_errpart[BMAX];                      // per-batch err sums
__device__ unsigned g_cnt[3];                          // barrier slots
__device__ unsigned g_dep;

// ---------------- fence-free barrier primitives ------------------------------
__device__ __forceinline__ void arrive_release(unsigned* p) {
    asm volatile("red.release.gpu.add.u32 [%0], 1;" :: "l"(p) : "memory");
}
__device__ __forceinline__ unsigned poll_acquire(unsigned* p) {
    unsigned v;
    asm volatile("ld.acquire.gpu.u32 %0, [%1];" : "=r"(v) : "l"(p) : "memory");
    return v;
}

__device__ __forceinline__ void gbar_slot(int s, int blk) {
    __syncthreads();
    if (threadIdx.x == 0) {
        arrive_release(&g_cnt[s]);
        while (poll_acquire(&g_cnt[s]) < (unsigned)NB) { }
        if (blk == 0) g_cnt[(s + 2) % 3] = 0;
    }
    __syncthreads();
}

__device__ __forceinline__ void gbar_exit(int s, int blk) {
    __syncthreads();
    if (threadIdx.x == 0) {
        arrive_release(&g_cnt[s]);
        while (poll_acquire(&g_cnt[s]) < (unsigned)NB) { }
        arrive_release(&g_dep);
        if (blk == 0) {
            while (poll_acquire(&g_dep) < (unsigned)NB) { }
            g_cnt[0] = 0; g_cnt[1] = 0; g_cnt[2] = 0;
            g_dep = 0;
        }
    }
    __syncthreads();
}

// ---------------- Kabsch (fp32, MUFU fast-math), reference semantics --------
__device__ void kabsch3x3f(const float* __restrict__ H,
                           const float* __restrict__ c1,
                           const float* __restrict__ c2,
                           float* __restrict__ Rout,
                           float* __restrict__ tout) {
    float A[3][3];
#pragma unroll
    for (int i = 0; i < 3; i++)
#pragma unroll
        for (int j = 0; j < 3; j++)
            A[i][j] = H[0 * 3 + i] * H[0 * 3 + j] +
                      H[1 * 3 + i] * H[1 * 3 + j] +
                      H[2 * 3 + i] * H[2 * 3 + j];
    float V[3][3] = {{1, 0, 0}, {0, 1, 0}, {0, 0, 1}};
#pragma unroll 1
    for (int sweep = 0; sweep < 8; sweep++) {
        float offd = A[0][1] * A[0][1] + A[0][2] * A[0][2] + A[1][2] * A[1][2];
        float diag = A[0][0] * A[0][0] + A[1][1] * A[1][1] + A[2][2] * A[2][2];
        if (offd < 1e-13f * diag + 1e-37f) break;   // converged to fp32 eps
#pragma unroll
        for (int pi = 0; pi < 3; pi++) {
            const int p = (pi == 2) ? 1 : 0;
            const int q = (pi == 0) ? 1 : 2;
            const int r = 3 - p - q;
            float apq = A[p][q];
            if (fabsf(apq) > 1e-30f) {
                float theta = __fdividef(A[q][q] - A[p][p], 2.0f * apq);
                float th2 = fmaf(theta, theta, 1.0f);
                float sq = (th2 < 3e37f) ? th2 * __frsqrt_rn(th2)
                                         : fabsf(theta);
                float tt = __fdividef(1.0f, fabsf(theta) + sq);
                if (theta < 0.0f) tt = -tt;
                float cc = __frsqrt_rn(fmaf(tt, tt, 1.0f));
                float ss = tt * cc;
                float app = A[p][p], aqq = A[q][q];
                A[p][p] = app - tt * apq;
                A[q][q] = aqq + tt * apq;
                A[p][q] = 0.0f; A[q][p] = 0.0f;
                float arp = A[r][p], arq = A[r][q];
                A[r][p] = cc * arp - ss * arq; A[p][r] = A[r][p];
                A[r][q] = ss * arp + cc * arq; A[q][r] = A[r][q];
#pragma unroll
                for (int k = 0; k < 3; k++) {
                    float vp = V[k][p], vq = V[k][q];
                    V[k][p] = cc * vp - ss * vq;
                    V[k][q] = ss * vp + cc * vq;
                }
            }
        }
    }
    float lam[3] = {A[0][0], A[1][1], A[2][2]};
#define CSWAP_(a, b)                                                       \
    if (lam[a] < lam[b]) {                                                 \
        float tl = lam[a]; lam[a] = lam[b]; lam[b] = tl;                   \
        float t0 = V[0][a]; V[0][a] = V[0][b]; V[0][b] = t0;               \
        float t1 = V[1][a]; V[1][a] = V[1][b]; V[1][b] = t1;               \
        float t2 = V[2][a]; V[2][a] = V[2][b]; V[2][b] = t2;               \
    }
    CSWAP_(0, 1); CSWAP_(0, 2); CSWAP_(1, 2);
#undef CSWAP_
    float U[3][3];
#pragma unroll
    for (int i = 0; i < 3; i++) {
        float ux = H[0] * V[0][i] + H[1] * V[1][i] + H[2] * V[2][i];
        float uy = H[3] * V[0][i] + H[4] * V[1][i] + H[5] * V[2][i];
        float uz = H[6] * V[0][i] + H[7] * V[1][i] + H[8] * V[2][i];
        float nn2 = ux * ux + uy * uy + uz * uz;
        if (nn2 > 1e-24f) {
            float inv = __frsqrt_rn(nn2);
            U[0][i] = ux * inv; U[1][i] = uy * inv; U[2][i] = uz * inv;
        } else {
            int a = (i + 1) % 3, b2 = (i + 2) % 3;
            U[0][i] = U[1][a] * U[2][b2] - U[2][a] * U[1][b2];
            U[1][i] = U[2][a] * U[0][b2] - U[0][a] * U[2][b2];
            U[2][i] = U[0][a] * U[1][b2] - U[1][a] * U[0][b2];
        }
    }
    float detU = U[0][0] * (U[1][1] * U[2][2] - U[1][2] * U[2][1]) -
                 U[0][1] * (U[1][0] * U[2][2] - U[1][2] * U[2][0]) +
                 U[0][2] * (U[1][0] * U[2][1] - U[1][1] * U[2][0]);
    float detV = V[0][0] * (V[1][1] * V[2][2] - V[1][2] * V[2][1]) -
                 V[0][1] * (V[1][0] * V[2][2] - V[1][2] * V[2][0]) +
                 V[0][2] * (V[1][0] * V[2][1] - V[1][1] * V[2][0]);
    float d = (detU * detV < 0.0f) ? -1.0f : 1.0f;
    V[2][2] *= d;
#pragma unroll
    for (int j = 0; j < 3; j++)
#pragma unroll
        for (int k = 0; k < 3; k++)
            Rout[j * 3 + k] =
                U[k][0] * V[j][0] + U[k][1] * V[j][1] + U[k][2] * V[j][2];
#pragma unroll
    for (int k = 0; k < 3; k++)
        tout[k] = c2[k] - (c1[0] * Rout[0 * 3 + k] +
                           c1[1] * Rout[1 * 3 + k] +
                           c1[2] * Rout[2 * 3 + k]);
}

// ---------------- block-level NV-way sum helper (NT threads) ----------------
template <int NV>
__device__ void block_reduce(float* acc, float* sfin, float (*sred)[16]) {
    int tid = threadIdx.x;
#pragma unroll
    for (int v = 0; v < NV; v++)
#pragma unroll
        for (int off = 16; off > 0; off >>= 1)
            acc[v] += __shfl_down_sync(0xFFFFFFFFu, acc[v], off);
    int w = tid >> 5, lane = tid & 31;
    if (lane == 0)
#pragma unroll
        for (int v = 0; v < NV; v++) sred[w][v] = acc[v];
    __syncthreads();
    if (tid < NV) {
        float sv = 0.0f;
#pragma unroll
        for (int k = 0; k < NT / 32; k++) sv += sred[k][tid];
        sfin[tid] = sv;
    }
    __syncthreads();
}

// build NN-ready form from coordinates
__device__ __forceinline__ float4 nnform(float x, float y, float z) {
    float4 v;
    v.w = x * x + y * y + z * z;
    v.x = -2.0f * x; v.y = -2.0f * y; v.z = -2.0f * z;
    return v;
}

// ---------------- the whole ICP in one persistent kernel --------------------
__global__ __launch_bounds__(NT, 1) void icp_kernel(const float* __restrict__ p1,
                                                    const float* __restrict__ p2,
                                                    float* __restrict__ out,
                                                    int N, int B) {
    __shared__ float4 sref[RTL];                    // 8 KB: NN-ready refs
    __shared__ unsigned long long skey[8][QTL];     // 16 KB
    __shared__ float sred[NT / 32][16];
    __shared__ float sfin[16];
    __shared__ float sRt[12];
    __shared__ int sdone;
    int tid = threadIdx.x, blk = blockIdx.x;
    int kbar = 0;
    int total = B * N;
    double prev_err = 0.0;                          // tracked by tid 0 only

    // ---- init: g_pc4 = NN-form(p1), both pack buffers = inf (all via L2) ---
    for (int i = blk * NT + tid; i < total; i += NB * NT) {
        float x = p1[i * 3 + 0], y = p1[i * 3 + 1], z = p1[i * 3 + 2];
        __stcg(&g_pc4[i], nnform(x, y, z));
        __stcg(&g_pack[0][i], ~0ull);
        __stcg(&g_pack[1][i], ~0ull);
    }
    gbar_slot(kbar % 3, blk); kbar++;

    int nIT = (N + QTL - 1) / QTL;
    int nJC = (N + RTL - 1) / RTL;
    int ntiles = B * nIT * nJC;

    for (int it = 0; it < MAXIT; it++) {
        // done check: every block computes the same mean from g_errpart
        if (it > 0) {
            if (tid == 0) {
                double s = 0.0;
                for (int bb = 0; bb < B; bb++)
                    s += (double)__ldcg(&g_errpart[bb]);
                double mean = s / (double)(B * N);
                sdone = (fabs(prev_err - mean) < TOLD) ? 1 : 0;
                prev_err = mean;
            }
            __syncthreads();
            if (sdone) break;                       // uniform across blocks
        }
        int par = it & 1;
        unsigned long long* pk_cur = g_pack[par];
        unsigned long long* pk_nxt = g_pack[par ^ 1];

        // ---- NN phase: tile = 256 queries x 512 refs; 4 queries/thread ----
        for (int tile = blk; tile < ntiles; tile += NB) {
            int b = tile / (nIT * nJC);
            int r = tile % (nIT * nJC);
            int ti = r / nJC, tj = r % nJC;
            int j0 = tj * RTL;
            __syncthreads();                       // smem reuse guard
            // ref load: pure LDG.128 -> STS.128 copy (NN form precomputed)
            for (int j = tid; j < RTL; j += NT) {
                int jj = j0 + j;
                float4 v;
                if (jj < N) {
                    v = __ldcg(&g_pc4[b * N + jj]);
                } else { v.x = 0.f; v.y = 0.f; v.z = 0.f; v.w = 3.0e38f; }
                sref[j] = v;
            }
            __syncthreads();

            int qg = tid & 63;                     // query group 0..63
            int c = tid >> 6;                      // ref chunk 0..7
            int i0 = ti * QTL + qg * 4;
            float qx[4], qy[4], qz[4];
            bool qv = (i0 + 3 < N);
            if (qv) {
                // 4 consecutive queries = 48B aligned -> 3x LDG.128 (L1 hot)
                const float4* qp =
                    (const float4*)&p2[(b * N + i0) * 3];
                float4 a0 = qp[0], a1 = qp[1], a2 = qp[2];
                qx[0] = a0.x; qy[0] = a0.y; qz[0] = a0.z;
                qx[1] = a0.w; qy[1] = a1.x; qz[1] = a1.y;
                qx[2] = a1.z; qy[2] = a1.w; qz[2] = a2.x;
                qx[3] = a2.y; qy[3] = a2.z; qz[3] = a2.w;
            } else {
#pragma unroll
                for (int k = 0; k < 4; k++) {
                    int i = i0 + k;
                    if (i < N) {
                        const float* qq = &p2[(b * N + i) * 3];
                        qx[k] = qq[0]; qy[k] = qq[1]; qz[k] = qq[2];
                    } else { qx[k] = 0.f; qy[k] = 0.f; qz[k] = 0.f; }
                }
            }
            // ---- 5-op/pair argmin: index packed into score mantissa LSBs ---
            // key = bitcast((bits(sc) & ~63) | j); bs = fminf(bs, key).
            // Quantizes score at 2^-17 relative; near-tie winners may differ
            // (benign), exact d2 recomputed for the winner below.
            float bs[4] = {3.4e38f, 3.4e38f, 3.4e38f, 3.4e38f};
            int jb = c * RCH;
#pragma unroll 4
            for (int j = 0; j < RCH; j++) {
                float4 s = sref[jb + j];
#pragma unroll
                for (int k = 0; k < 4; k++) {
                    float sc = fmaf(qx[k], s.x,
                                    fmaf(qy[k], s.y, fmaf(qz[k], s.z, s.w)));
                    unsigned u = (__float_as_uint(sc) & ~63u) | (unsigned)j;
                    bs[k] = fminf(bs[k], __uint_as_float(u));
                }
            }
#pragma unroll
            for (int k = 0; k < 4; k++) {
                unsigned u = __float_as_uint(bs[k]);
                unsigned bj = u & 63u;              // local winner index
                unsigned sb = u & ~63u;             // quantized score bits
                unsigned ub = sb ^ ((sb & 0x80000000u) ? 0xFFFFFFFFu
                                                       : 0x80000000u);
                skey[c][qg * 4 + k] =
                    ((unsigned long long)ub << 32) | (unsigned)(jb + bj);
            }
            __syncthreads();
            // combine 8 chunks per query; recompute exact d2 for the winner
            if (tid < QTL) {
                int i = ti * QTL + tid;
                if (i < N) {
                    unsigned long long kmin = skey[0][tid];
#pragma unroll
                    for (int cc = 1; cc < 8; cc++) {
                        unsigned long long k2 = skey[cc][tid];
                        if (k2 < kmin) kmin = k2;
                    }
                    int jloc = (int)(unsigned)(kmin & 0xFFFFFFFFull);
                    float4 s = sref[jloc];
                    float x = -0.5f * s.x, y = -0.5f * s.y, z = -0.5f * s.z;
                    const float* qq = &p2[(b * N + i) * 3];
                    float dx = qq[0] - x, dy = qq[1] - y, dz = qq[2] - z;
                    float d2 = fmaf(dx, dx, fmaf(dy, dy, dz * dz));
                    unsigned long long pk =
                        ((unsigned long long)__float_as_uint(d2) << 32) |
                        (unsigned)(j0 + jloc);
                    atomicMin(&pk_cur[b * N + i], pk);
                }
            }
        }
        gbar_slot(kbar % 3, blk); kbar++;

        // ---- phase B (blocks 0..B-1): hsum+err + kabsch + apply + reset ----
        if (blk < B) {
            int b = blk;
            float acc[16];
#pragma unroll
            for (int v = 0; v < 16; v++) acc[v] = 0.0f;
            for (int n = tid; n < N; n += NT) {
                float4 pc4 = __ldcg(&g_pc4[b * N + n]);
                float ax = -0.5f * pc4.x, ay = -0.5f * pc4.y,
                      az = -0.5f * pc4.z;                  // exact recovery
                unsigned long long pkL = __ldcg(&pk_cur[(B - 1) * N + n]);
                int mi = (int)(unsigned)(pkL & 0xFFFFFFFFull);
                const float* m = &p2[(b * N + mi) * 3];
                float bx = m[0], by = m[1], bz = m[2];
                unsigned long long pkb = __ldcg(&pk_cur[b * N + n]);
                float d2 = __uint_as_float((unsigned)(pkb >> 32));
                acc[0] += ax;  acc[1] += ay;  acc[2] += az;
                acc[3] += bx;  acc[4] += by;  acc[5] += bz;
                acc[6] += bx * ax;  acc[7] += bx * ay;  acc[8] += bx * az;
                acc[9] += by * ax;  acc[10] += by * ay; acc[11] += by * az;
                acc[12] += bz * ax; acc[13] += bz * ay; acc[14] += bz * az;
                acc[15] += sqrtf(d2);
            }
            block_reduce<16>(acc, sfin, sred);
            if (tid == 0) {
                __stcg(&g_errpart[b], sfin[15]);
                float invN = 1.0f / (float)N;
                float H[9], c1[3], c2[3], R[9], tv[3];
#pragma unroll
                for (int j = 0; j < 3; j++)
#pragma unroll
                    for (int k = 0; k < 3; k++)
                        H[j * 3 + k] = sfin[6 + j * 3 + k] -
                                       sfin[3 + j] * sfin[k] * invN;
#pragma unroll
                for (int k = 0; k < 3; k++) {
                    c1[k] = sfin[k] * invN;
                    c2[k] = sfin[3 + k] * invN;
                }
                kabsch3x3f(H, c1, c2, R, tv);
#pragma unroll
                for (int v = 0; v < 9; v++) sRt[v] = R[v];
#pragma unroll
                for (int v = 0; v < 3; v++) sRt[9 + v] = tv[v];
            }
            __syncthreads();
            // apply to own batch (store NN form) + reset other pack buffer
            for (int n = tid; n < N; n += NT) {
                float4 pc4 = __ldcg(&g_pc4[b * N + n]);
                float x = -0.5f * pc4.x, y = -0.5f * pc4.y,
                      z = -0.5f * pc4.z;                   // exact recovery
                float nx = x * sRt[0] + y * sRt[3] + z * sRt[6] + sRt[9];
                float ny = x * sRt[1] + y * sRt[4] + z * sRt[7] + sRt[10];
                float nz = x * sRt[2] + y * sRt[5] + z * sRt[8] + sRt[11];
                __stcg(&g_pc4[b * N + n], nnform(nx, ny, nz));
                __stcg(&pk_nxt[b * N + n], ~0ull);
            }
        }
        gbar_slot(kbar % 3, blk); kbar++;
    }

    gbar_exit(kbar % 3, blk);   // also resets counters for graph replay

    // ---- final transform: q1 = p1, q2 = temp_pc ----
    if (blk >= B) return;
    {
        int b = blk;
        float acc[15];
#pragma unroll
        for (int v = 0; v < 15; v++) acc[v] = 0.0f;
        for (int n = tid; n < N; n += NT) {
            const float* a = &p1[(b * N + n) * 3];
            float4 pc4 = __ldcg(&g_pc4[b * N + n]);
            float ax = a[0], ay = a[1], az = a[2];
            float bx = -0.5f * pc4.x, by = -0.5f * pc4.y, bz = -0.5f * pc4.z;
            acc[0] += ax;  acc[1] += ay;  acc[2] += az;
            acc[3] += bx;  acc[4] += by;  acc[5] += bz;
            acc[6] += bx * ax;  acc[7] += bx * ay;  acc[8] += bx * az;
            acc[9] += by * ax;  acc[10] += by * ay; acc[11] += by * az;
            acc[12] += bz * ax; acc[13] += bz * ay; acc[14] += bz * az;
        }
        block_reduce<15>(acc, sfin, sred);
        if (tid == 0) {
            float invN = 1.0f / (float)N;
            float H[9], c1[3], c2[3], R[9], tv[3];
#pragma unroll
            for (int j = 0; j < 3; j++)
#pragma unroll
                for (int k = 0; k < 3; k++)
                    H[j * 3 + k] = sfin[6 + j * 3 + k] -
                                   sfin[3 + j] * sfin[k] * invN;
#pragma unroll
            for (int k = 0; k < 3; k++) {
                c1[k] = sfin[k] * invN;
                c2[k] = sfin[3 + k] * invN;
            }
            kabsch3x3f(H, c1, c2, R, tv);
#pragma unroll
            for (int j = 0; j < 3; j++) {
                out[b * 12 + j * 4 + 0] = R[j * 3 + 0];
                out[b * 12 + j * 4 + 1] = R[j * 3 + 1];
                out[b * 12 + j * 4 + 2] = R[j * 3 + 2];
                out[b * 12 + j * 4 + 3] = tv[j];
            }
        }
    }
}

extern "C" void kernel_launch(void* const* d_in, const int* in_sizes, int n_in,
                              void* d_out, int out_size) {
    const float* p1 = (const float*)d_in[0];
    const float* p2 = (const float*)d_in[1];
    float* out = (float*)d_out;

    int B = out_size / 12;            // T is (B,3,4)
    if (B < 1) B = 1;
    if (B > BMAX) B = BMAX;
    int N = in_sizes[0] / (B * 3);    // points per batch
    if (N > NMAX) N = NMAX;

    icp_kernel<<<NB, NT>>>(p1, p2, out, N, B);
}